// round 1
// baseline (speedup 1.0000x reference)
#include <cuda_runtime.h>

#define BATCH 4
#define SEQ   2048
#define EMB   1024
#define HD    64

// Scratch (allocation-free: __device__ globals)
static __device__ float g_q[BATCH * SEQ * HD];       // 2 MB
static __device__ float g_k[BATCH * SEQ * HD];       // 2 MB
static __device__ float g_s[BATCH * SEQ * SEQ];      // 64 MB: scores -> weights (in place)
static __device__ float g_m[BATCH * SEQ];            // per-(b,key-col) max over q
static __device__ float g_rz[BATCH * SEQ];           // per-(b,key-col) 1/sum(exp)

// ---------------------------------------------------------------------------
// Kernel 1: q = h@Wq + bq, k = h@Wk + bk   (M=8192, K=1024, N=64, fused)
// ---------------------------------------------------------------------------
__global__ __launch_bounds__(256) void proj_kernel(
    const float* __restrict__ h, const float* __restrict__ Wq,
    const float* __restrict__ bq, const float* __restrict__ Wk,
    const float* __restrict__ bk)
{
    __shared__ float sH[64][17];     // padded to avoid bank conflicts
    __shared__ float sWq[16][64];
    __shared__ float sWk[16][64];
    const int tid = threadIdx.x;
    const int tx = tid & 15, ty = tid >> 4;
    const int row0 = blockIdx.x * 64;

    const int hr = tid >> 2, hc = (tid & 3) * 4;     // h tile loader: 64x16
    const int wr = tid >> 4, wc = (tid & 15) * 4;    // W tile loader: 16x64

    float accq[4][4] = {};
    float acck[4][4] = {};

    for (int e0 = 0; e0 < EMB; e0 += 16) {
        float4 v = *(const float4*)(h + (size_t)(row0 + hr) * EMB + e0 + hc);
        sH[hr][hc + 0] = v.x; sH[hr][hc + 1] = v.y;
        sH[hr][hc + 2] = v.z; sH[hr][hc + 3] = v.w;
        *(float4*)&sWq[wr][wc] = *(const float4*)(Wq + (size_t)(e0 + wr) * HD + wc);
        *(float4*)&sWk[wr][wc] = *(const float4*)(Wk + (size_t)(e0 + wr) * HD + wc);
        __syncthreads();
        #pragma unroll
        for (int kk = 0; kk < 16; kk++) {
            float a[4], bqv[4], bkv[4];
            #pragma unroll
            for (int i = 0; i < 4; i++) a[i] = sH[ty * 4 + i][kk];
            #pragma unroll
            for (int j = 0; j < 4; j++) { bqv[j] = sWq[kk][tx * 4 + j]; bkv[j] = sWk[kk][tx * 4 + j]; }
            #pragma unroll
            for (int i = 0; i < 4; i++)
                #pragma unroll
                for (int j = 0; j < 4; j++) {
                    accq[i][j] += a[i] * bqv[j];
                    acck[i][j] += a[i] * bkv[j];
                }
        }
        __syncthreads();
    }
    #pragma unroll
    for (int i = 0; i < 4; i++) {
        const int r = row0 + ty * 4 + i;
        #pragma unroll
        for (int j = 0; j < 4; j++) {
            const int c = tx * 4 + j;
            g_q[r * HD + c] = accq[i][j] + bq[c];
            g_k[r * HD + c] = acck[i][j] + bk[c];
        }
    }
}

// ---------------------------------------------------------------------------
// Kernel 2: scores[b,m,n] = (q[b,m,:] . k[b,n,:]) * 0.125   (K=64 in smem)
// ---------------------------------------------------------------------------
__global__ __launch_bounds__(256) void score_kernel()
{
    __shared__ float sQT[64][65];   // [d][row], padded
    __shared__ float sKT[64][65];   // [d][col], padded
    const int tid = threadIdx.x;
    const int tx = tid & 15, ty = tid >> 4;
    const int b  = blockIdx.z;
    const int m0 = blockIdx.y * 64;
    const int n0 = blockIdx.x * 64;
    const float* qb = g_q + (size_t)b * SEQ * HD;
    const float* kb = g_k + (size_t)b * SEQ * HD;

    {
        const int r = tid >> 2;
        const int cq = (tid & 3) * 16;
        #pragma unroll
        for (int u = 0; u < 4; u++) {
            const int c = cq + u * 4;
            float4 vq = *(const float4*)(qb + (size_t)(m0 + r) * HD + c);
            float4 vk = *(const float4*)(kb + (size_t)(n0 + r) * HD + c);
            sQT[c + 0][r] = vq.x; sQT[c + 1][r] = vq.y; sQT[c + 2][r] = vq.z; sQT[c + 3][r] = vq.w;
            sKT[c + 0][r] = vk.x; sKT[c + 1][r] = vk.y; sKT[c + 2][r] = vk.z; sKT[c + 3][r] = vk.w;
        }
    }
    __syncthreads();

    float acc[4][4] = {};
    #pragma unroll 8
    for (int kk = 0; kk < 64; kk++) {
        float a[4], bb[4];
        #pragma unroll
        for (int i = 0; i < 4; i++) a[i] = sQT[kk][ty * 4 + i];
        #pragma unroll
        for (int j = 0; j < 4; j++) bb[j] = sKT[kk][tx * 4 + j];
        #pragma unroll
        for (int i = 0; i < 4; i++)
            #pragma unroll
            for (int j = 0; j < 4; j++)
                acc[i][j] += a[i] * bb[j];
    }

    float* srow = g_s + (size_t)b * SEQ * SEQ;
    #pragma unroll
    for (int i = 0; i < 4; i++) {
        float4 o = make_float4(acc[i][0] * 0.125f, acc[i][1] * 0.125f,
                               acc[i][2] * 0.125f, acc[i][3] * 0.125f);
        *(float4*)(srow + (size_t)(m0 + ty * 4 + i) * SEQ + n0 + tx * 4) = o;
    }
}

// ---------------------------------------------------------------------------
// Kernel 3: per-(b, key-column) stats for softmax over the QUERY axis
// ---------------------------------------------------------------------------
__global__ __launch_bounds__(256) void colstat_kernel()
{
    const int b = blockIdx.y;
    const int k = blockIdx.x * 256 + threadIdx.x;
    const float* col = g_s + (size_t)b * SEQ * SEQ + k;
    float m = -3.0e38f;
    #pragma unroll 8
    for (int q = 0; q < SEQ; q++) m = fmaxf(m, col[(size_t)q * SEQ]);
    float z = 0.0f;
    #pragma unroll 8
    for (int q = 0; q < SEQ; q++) z += __expf(col[(size_t)q * SEQ] - m);
    g_m[b * SEQ + k]  = m;
    g_rz[b * SEQ + k] = 1.0f / z;
}

// ---------------------------------------------------------------------------
// Kernel 4: in-place normalize: w = exp(s - m_col) * rz_col
// ---------------------------------------------------------------------------
__global__ __launch_bounds__(256) void norm_kernel()
{
    const int idx = (blockIdx.x * 256 + threadIdx.x) * 4;  // < 2^24, fits int
    const int b = idx >> 22;                // SEQ*SEQ = 2^22
    const int k = idx & (SEQ - 1);
    const int base = b * SEQ + k;
    float4 v = *(float4*)(g_s + idx);
    v.x = __expf(v.x - g_m[base + 0]) * g_rz[base + 0];
    v.y = __expf(v.y - g_m[base + 1]) * g_rz[base + 1];
    v.z = __expf(v.z - g_m[base + 2]) * g_rz[base + 2];
    v.w = __expf(v.w - g_m[base + 3]) * g_rz[base + 3];
    *(float4*)(g_s + idx) = v;
}

// ---------------------------------------------------------------------------
// Kernel 5: out[b] = W[b] (2048x2048) @ h[b] (2048x1024), fp32 via fma.rn.f32x2
// 128x128x8 tiles, 256 threads, 8x8 microtile, packed f32x2 accumulators.
// ---------------------------------------------------------------------------
__global__ __launch_bounds__(256, 2) void out_gemm_kernel(
    const float* __restrict__ hmat, float* __restrict__ out)
{
    __shared__ float As[8][132];    // A transposed: As[k][m], pad keeps stores conflict-free
    __shared__ float Bs[8][128];
    const int tid = threadIdx.x;
    const int tx = tid & 15, ty = tid >> 4;
    const int b  = blockIdx.z;
    const int m0 = blockIdx.y * 128;
    const int n0 = blockIdx.x * 128;
    const float* A = g_s + (size_t)b * SEQ * SEQ;    // weights, ld = SEQ
    const float* B = hmat + (size_t)b * SEQ * EMB;   // h, ld = EMB
    float* C = out + (size_t)b * SEQ * EMB;

    const int ar = tid >> 1, ak = (tid & 1) * 4;     // A loader: 128 rows x 8 k
    const int br = tid >> 5, bc = (tid & 31) * 4;    // B loader: 8 rows x 128 n

    unsigned long long acc[8][4];
    #pragma unroll
    for (int i = 0; i < 8; i++)
        #pragma unroll
        for (int j = 0; j < 4; j++) acc[i][j] = 0ull;

    for (int k0 = 0; k0 < SEQ; k0 += 8) {
        float4 av4 = *(const float4*)(A + (size_t)(m0 + ar) * SEQ + k0 + ak);
        float4 bv4 = *(const float4*)(B + (size_t)(k0 + br) * EMB + n0 + bc);
        As[ak + 0][ar] = av4.x; As[ak + 1][ar] = av4.y;
        As[ak + 2][ar] = av4.z; As[ak + 3][ar] = av4.w;
        *(float4*)&Bs[br][bc] = bv4;
        __syncthreads();
        #pragma unroll
        for (int kk = 0; kk < 8; kk++) {
            float a[8];
            *(float4*)&a[0] = *(const float4*)&As[kk][ty * 8];
            *(float4*)&a[4] = *(const float4*)&As[kk][ty * 8 + 4];
            unsigned long long b2[4];
            {
                ulonglong2 t0 = *(const ulonglong2*)&Bs[kk][tx * 8];
                ulonglong2 t1 = *(const ulonglong2*)&Bs[kk][tx * 8 + 4];
                b2[0] = t0.x; b2[1] = t0.y; b2[2] = t1.x; b2[3] = t1.y;
            }
            #pragma unroll
            for (int i = 0; i < 8; i++) {
                unsigned long long a2;
                const unsigned int ai = __float_as_uint(a[i]);
                asm("mov.b64 %0, {%1, %1};" : "=l"(a2) : "r"(ai));
                #pragma unroll
                for (int j = 0; j < 4; j++)
                    asm("fma.rn.f32x2 %0, %1, %2, %0;" : "+l"(acc[i][j]) : "l"(a2), "l"(b2[j]));
            }
        }
        __syncthreads();
    }

    #pragma unroll
    for (int i = 0; i < 8; i++) {
        union { unsigned long long u; float2 f; } c0, c1, c2, c3;
        c0.u = acc[i][0]; c1.u = acc[i][1]; c2.u = acc[i][2]; c3.u = acc[i][3];
        float* dst = C + (size_t)(m0 + ty * 8 + i) * EMB + n0 + tx * 8;
        *(float4*)(dst)     = make_float4(c0.f.x, c0.f.y, c1.f.x, c1.f.y);
        *(float4*)(dst + 4) = make_float4(c2.f.x, c2.f.y, c3.f.x, c3.f.y);
    }
}

// ---------------------------------------------------------------------------
extern "C" void kernel_launch(void* const* d_in, const int* in_sizes, int n_in,
                              void* d_out, int out_size)
{
    const float* h  = (const float*)d_in[0];
    const float* Wq = (const float*)d_in[1];
    const float* bq = (const float*)d_in[2];
    const float* Wk = (const float*)d_in[3];
    const float* bk = (const float*)d_in[4];
    // d_in[5] = Wv, d_in[6] = bv : unused by the reference semantics
    float* out = (float*)d_out;

    proj_kernel<<<(BATCH * SEQ) / 64, 256>>>(h, Wq, bq, Wk, bk);
    score_kernel<<<dim3(SEQ / 64, SEQ / 64, BATCH), 256>>>();
    colstat_kernel<<<dim3(SEQ / 256, BATCH), 256>>>();
    norm_kernel<<<(BATCH * SEQ * SEQ) / (4 * 256), 256>>>();
    out_gemm_kernel<<<dim3(EMB / 128, SEQ / 128, BATCH), 256>>>(h, out);
}

// round 3
// speedup vs baseline: 2.0999x; 2.0999x over previous
#include <cuda_runtime.h>
#include <cstdint>

#define BATCH 4
#define SEQ   2048
#define EMB   1024
#define HD    64

// Scratch (allocation-free: __device__ globals)
static __device__ float g_q[BATCH * SEQ * HD];       // 2 MB
static __device__ float g_k[BATCH * SEQ * HD];       // 2 MB
static __device__ float g_s[BATCH * SEQ * SEQ];      // 64 MB: scores -> tf32 weights (in place)
static __device__ float g_hr[BATCH * SEQ * EMB];     // 32 MB: h rounded to tf32, [B][S][E]
static __device__ float g_m[BATCH * SEQ];            // per-(b,key-col) max over q
static __device__ float g_rz[BATCH * SEQ];           // per-(b,key-col) 1/sum(exp)

__device__ __forceinline__ float tf32_rna(float x) {
    uint32_t t;
    asm("cvt.rna.tf32.f32 %0, %1;" : "=r"(t) : "f"(x));
    return __uint_as_float(t);
}

// ---------------------------------------------------------------------------
// Kernel 1: q = h@Wq + bq, k = h@Wk + bk   (M=8192, K=1024, N=64, fused)
// ---------------------------------------------------------------------------
__global__ __launch_bounds__(256) void proj_kernel(
    const float* __restrict__ h, const float* __restrict__ Wq,
    const float* __restrict__ bq, const float* __restrict__ Wk,
    const float* __restrict__ bk)
{
    __shared__ float sH[64][17];
    __shared__ float sWq[16][64];
    __shared__ float sWk[16][64];
    const int tid = threadIdx.x;
    const int tx = tid & 15, ty = tid >> 4;
    const int row0 = blockIdx.x * 64;

    const int hr = tid >> 2, hc = (tid & 3) * 4;
    const int wr = tid >> 4, wc = (tid & 15) * 4;

    float accq[4][4] = {};
    float acck[4][4] = {};

    for (int e0 = 0; e0 < EMB; e0 += 16) {
        float4 v = *(const float4*)(h + (size_t)(row0 + hr) * EMB + e0 + hc);
        sH[hr][hc + 0] = v.x; sH[hr][hc + 1] = v.y;
        sH[hr][hc + 2] = v.z; sH[hr][hc + 3] = v.w;
        *(float4*)&sWq[wr][wc] = *(const float4*)(Wq + (size_t)(e0 + wr) * HD + wc);
        *(float4*)&sWk[wr][wc] = *(const float4*)(Wk + (size_t)(e0 + wr) * HD + wc);
        __syncthreads();
        #pragma unroll
        for (int kk = 0; kk < 16; kk++) {
            float a[4], bqv[4], bkv[4];
            #pragma unroll
            for (int i = 0; i < 4; i++) a[i] = sH[ty * 4 + i][kk];
            #pragma unroll
            for (int j = 0; j < 4; j++) { bqv[j] = sWq[kk][tx * 4 + j]; bkv[j] = sWk[kk][tx * 4 + j]; }
            #pragma unroll
            for (int i = 0; i < 4; i++)
                #pragma unroll
                for (int j = 0; j < 4; j++) {
                    accq[i][j] += a[i] * bqv[j];
                    acck[i][j] += a[i] * bkv[j];
                }
        }
        __syncthreads();
    }
    #pragma unroll
    for (int i = 0; i < 4; i++) {
        const int r = row0 + ty * 4 + i;
        #pragma unroll
        for (int j = 0; j < 4; j++) {
            const int c = tx * 4 + j;
            g_q[r * HD + c] = accq[i][j] + bq[c];
            g_k[r * HD + c] = acck[i][j] + bk[c];
        }
    }
}

// ---------------------------------------------------------------------------
// Kernel 1b: g_hr = tf32_round(h)
// ---------------------------------------------------------------------------
__global__ __launch_bounds__(256) void round_h_kernel(const float* __restrict__ h)
{
    const size_t idx = ((size_t)blockIdx.x * 256 + threadIdx.x) * 4;
    float4 v = *(const float4*)(h + idx);
    v.x = tf32_rna(v.x); v.y = tf32_rna(v.y);
    v.z = tf32_rna(v.z); v.w = tf32_rna(v.w);
    *(float4*)(g_hr + idx) = v;
}

// ---------------------------------------------------------------------------
// Kernel 2: scores[b,m,n] = (q[b,m,:] . k[b,n,:]) * 0.125   (K=64 in smem)
// ---------------------------------------------------------------------------
__global__ __launch_bounds__(256) void score_kernel()
{
    __shared__ float sQT[64][65];
    __shared__ float sKT[64][65];
    const int tid = threadIdx.x;
    const int tx = tid & 15, ty = tid >> 4;
    const int b  = blockIdx.z;
    const int m0 = blockIdx.y * 64;
    const int n0 = blockIdx.x * 64;
    const float* qb = g_q + (size_t)b * SEQ * HD;
    const float* kb = g_k + (size_t)b * SEQ * HD;

    {
        const int r = tid >> 2;
        const int cq = (tid & 3) * 16;
        #pragma unroll
        for (int u = 0; u < 4; u++) {
            const int c = cq + u * 4;
            float4 vq = *(const float4*)(qb + (size_t)(m0 + r) * HD + c);
            float4 vk = *(const float4*)(kb + (size_t)(n0 + r) * HD + c);
            sQT[c + 0][r] = vq.x; sQT[c + 1][r] = vq.y; sQT[c + 2][r] = vq.z; sQT[c + 3][r] = vq.w;
            sKT[c + 0][r] = vk.x; sKT[c + 1][r] = vk.y; sKT[c + 2][r] = vk.z; sKT[c + 3][r] = vk.w;
        }
    }
    __syncthreads();

    float acc[4][4] = {};
    #pragma unroll 8
    for (int kk = 0; kk < 64; kk++) {
        float a[4], bb[4];
        #pragma unroll
        for (int i = 0; i < 4; i++) a[i] = sQT[kk][ty * 4 + i];
        #pragma unroll
        for (int j = 0; j < 4; j++) bb[j] = sKT[kk][tx * 4 + j];
        #pragma unroll
        for (int i = 0; i < 4; i++)
            #pragma unroll
            for (int j = 0; j < 4; j++)
                acc[i][j] += a[i] * bb[j];
    }

    float* srow = g_s + (size_t)b * SEQ * SEQ;
    #pragma unroll
    for (int i = 0; i < 4; i++) {
        float4 o = make_float4(acc[i][0] * 0.125f, acc[i][1] * 0.125f,
                               acc[i][2] * 0.125f, acc[i][3] * 0.125f);
        *(float4*)(srow + (size_t)(m0 + ty * 4 + i) * SEQ + n0 + tx * 4) = o;
    }
}

// ---------------------------------------------------------------------------
// Kernel 3: per-(b, key-column) stats for softmax over the QUERY axis
// ---------------------------------------------------------------------------
__global__ __launch_bounds__(256) void colstat_kernel()
{
    const int b = blockIdx.y;
    const int k = blockIdx.x * 256 + threadIdx.x;
    const float* col = g_s + (size_t)b * SEQ * SEQ + k;
    float m = -3.0e38f;
    #pragma unroll 8
    for (int q = 0; q < SEQ; q++) m = fmaxf(m, col[(size_t)q * SEQ]);
    float z = 0.0f;
    #pragma unroll 8
    for (int q = 0; q < SEQ; q++) z += __expf(col[(size_t)q * SEQ] - m);
    g_m[b * SEQ + k]  = m;
    g_rz[b * SEQ + k] = 1.0f / z;
}

// ---------------------------------------------------------------------------
// Kernel 4: in-place normalize: w = tf32_round(exp(s - m_col) * rz_col)
// ---------------------------------------------------------------------------
__global__ __launch_bounds__(256) void norm_kernel()
{
    const int idx = (blockIdx.x * 256 + threadIdx.x) * 4;
    const int b = idx >> 22;
    const int k = idx & (SEQ - 1);
    const int base = b * SEQ + k;
    float4 v = *(float4*)(g_s + idx);
    v.x = tf32_rna(__expf(v.x - g_m[base + 0]) * g_rz[base + 0]);
    v.y = tf32_rna(__expf(v.y - g_m[base + 1]) * g_rz[base + 1]);
    v.z = tf32_rna(__expf(v.z - g_m[base + 2]) * g_rz[base + 2]);
    v.w = tf32_rna(__expf(v.w - g_m[base + 3]) * g_rz[base + 3]);
    *(float4*)(g_s + idx) = v;
}

// ---------------------------------------------------------------------------
// Kernel 5: out[b] = W[b] (2048x2048) @ h[b] (2048x1024), tf32 mma.sync.
// CTA tile 128x256, 8 warps (2x4), warp tile 64x64, K-chunk 32,
// cp.async double-buffered smem.
// smem strides: sA[m][36] words, sB[k][264] words -> conflict-free lds.
// ---------------------------------------------------------------------------
#define SA_STRIDE 36
#define SB_STRIDE 264
#define SA_BYTES  (128 * SA_STRIDE * 4)    // 18432
#define SB_BYTES  (32 * SB_STRIDE * 4)     // 33792
#define SMEM_A(p) ((p) * SA_BYTES)
#define SMEM_B(p) (2 * SA_BYTES + (p) * SB_BYTES)
#define SMEM_TOT  (2 * SA_BYTES + 2 * SB_BYTES)   // 104448

__device__ __forceinline__ void cp_async16(uint32_t saddr, const void* gaddr) {
    asm volatile("cp.async.cg.shared.global [%0], [%1], 16;"
                 :: "r"(saddr), "l"(gaddr) : "memory");
}
__device__ __forceinline__ uint32_t smem_u32(const void* p) {
    uint32_t a;
    asm("{ .reg .u64 t; cvta.to.shared.u64 t, %1; cvt.u32.u64 %0, t; }"
        : "=r"(a) : "l"(p));
    return a;
}
__device__ __forceinline__ void mma_tf32(float* c, const uint32_t* a, const uint32_t* b) {
    asm volatile(
        "mma.sync.aligned.m16n8k8.row.col.f32.tf32.tf32.f32 "
        "{%0,%1,%2,%3}, {%4,%5,%6,%7}, {%8,%9}, {%0,%1,%2,%3};"
        : "+f"(c[0]), "+f"(c[1]), "+f"(c[2]), "+f"(c[3])
        : "r"(a[0]), "r"(a[1]), "r"(a[2]), "r"(a[3]), "r"(b[0]), "r"(b[1]));
}

__global__ __launch_bounds__(256) void out_gemm_mma_kernel(float* __restrict__ out)
{
    extern __shared__ char smem[];
    const uint32_t smem_base = smem_u32(smem);
    const int tid  = threadIdx.x;
    const int wid  = tid >> 5;
    const int lane = tid & 31;
    const int la   = lane >> 2;       // 0..7
    const int lb   = lane & 3;        // 0..3
    const int wm   = (wid & 1) * 64;  // warp m origin in tile
    const int wn   = (wid >> 1) * 64; // warp n origin in tile

    const int b  = blockIdx.z;
    const int m0 = blockIdx.y * 128;
    const int n0 = blockIdx.x * 256;
    const float* A = g_s  + (size_t)b * SEQ * SEQ + (size_t)m0 * SEQ;  // [128, 2048] row-major
    const float* B = g_hr + (size_t)b * SEQ * EMB + n0;                // [2048, (256 cols)] row-major

    float acc[4][8][4];
    #pragma unroll
    for (int i = 0; i < 4; i++)
        #pragma unroll
        for (int j = 0; j < 8; j++)
            #pragma unroll
            for (int q = 0; q < 4; q++) acc[i][j][q] = 0.0f;

    // per-thread cp.async source/dest decomposition
    const int am = tid >> 3;          // A row (loads 1 of 8 float4 per row; 4 iters cover 128 rows? no:
                                      // 256 threads * 4 iters = 1024 f4 = 128 rows x 8)
    const int ak = (tid & 7) * 4;     // A col (floats)
    const int bk = tid >> 6;          // B row base (8 iters x 4 rows)
    const int bn = (tid & 63) * 4;    // B col (floats)

    // prologue: load chunk 0 into buffer 0
    {
        #pragma unroll
        for (int i = 0; i < 4; i++) {
            const int m = am + i * 32;
            cp_async16(smem_base + SMEM_A(0) + m * (SA_STRIDE * 4) + ak * 4,
                       A + (size_t)m * SEQ + ak);
        }
        #pragma unroll
        for (int i = 0; i < 8; i++) {
            const int k = bk + i * 4;
            cp_async16(smem_base + SMEM_B(0) + k * (SB_STRIDE * 4) + bn * 4,
                       B + (size_t)k * EMB + bn);
        }
        asm volatile("cp.async.commit_group;" ::: "memory");
    }

    for (int c = 0; c < SEQ / 32; ++c) {
        const int p = c & 1;
        if (c < SEQ / 32 - 1) {
            const int k0 = (c + 1) * 32;
            #pragma unroll
            for (int i = 0; i < 4; i++) {
                const int m = am + i * 32;
                cp_async16(smem_base + SMEM_A(p ^ 1) + m * (SA_STRIDE * 4) + ak * 4,
                           A + (size_t)m * SEQ + k0 + ak);
            }
            #pragma unroll
            for (int i = 0; i < 8; i++) {
                const int k = bk + i * 4;
                cp_async16(smem_base + SMEM_B(p ^ 1) + k * (SB_STRIDE * 4) + bn * 4,
                           B + (size_t)(k0 + k) * EMB + bn);
            }
            asm volatile("cp.async.commit_group;" ::: "memory");
            asm volatile("cp.async.wait_group 1;" ::: "memory");
        } else {
            asm volatile("cp.async.wait_group 0;" ::: "memory");
        }
        __syncthreads();

        const uint32_t* sA = (const uint32_t*)(smem + SMEM_A(p));
        const uint32_t* sB = (const uint32_t*)(smem + SMEM_B(p));

        #pragma unroll
        for (int kf = 0; kf < 4; kf++) {
            uint32_t afr[4][4];
            #pragma unroll
            for (int mf = 0; mf < 4; mf++) {
                const int r = wm + mf * 16 + la;
                const int cc = kf * 8 + lb;
                afr[mf][0] = sA[r * SA_STRIDE + cc];
                afr[mf][1] = sA[(r + 8) * SA_STRIDE + cc];
                afr[mf][2] = sA[r * SA_STRIDE + cc + 4];
                afr[mf][3] = sA[(r + 8) * SA_STRIDE + cc + 4];
            }
            uint32_t bfr[8][2];
            #pragma unroll
            for (int nf = 0; nf < 8; nf++) {
                const int col = wn + nf * 8 + la;
                const int kk = kf * 8 + lb;
                bfr[nf][0] = sB[kk * SB_STRIDE + col];
                bfr[nf][1] = sB[(kk + 4) * SB_STRIDE + col];
            }
            #pragma unroll
            for (int mf = 0; mf < 4; mf++)
                #pragma unroll
                for (int nf = 0; nf < 8; nf++)
                    mma_tf32(acc[mf][nf], afr[mf], bfr[nf]);
        }
        __syncthreads();
    }

    // epilogue
    float* C = out + (size_t)b * SEQ * EMB;
    #pragma unroll
    for (int mf = 0; mf < 4; mf++) {
        const int r = m0 + wm + mf * 16 + la;
        #pragma unroll
        for (int nf = 0; nf < 8; nf++) {
            const int col = n0 + wn + nf * 8 + lb * 2;
            *(float2*)(C + (size_t)r * EMB + col)       = make_float2(acc[mf][nf][0], acc[mf][nf][1]);
            *(float2*)(C + (size_t)(r + 8) * EMB + col) = make_float2(acc[mf][nf][2], acc[mf][nf][3]);
        }
    }
}

// ---------------------------------------------------------------------------
extern "C" void kernel_launch(void* const* d_in, const int* in_sizes, int n_in,
                              void* d_out, int out_size)
{
    const float* h  = (const float*)d_in[0];
    const float* Wq = (const float*)d_in[1];
    const float* bq = (const float*)d_in[2];
    const float* Wk = (const float*)d_in[3];
    const float* bk = (const float*)d_in[4];
    float* out = (float*)d_out;

    static int smem_set = 0;
    if (!smem_set) {
        cudaFuncSetAttribute(out_gemm_mma_kernel,
                             cudaFuncAttributeMaxDynamicSharedMemorySize, SMEM_TOT);
        smem_set = 1;
    }

    proj_kernel<<<(BATCH * SEQ) / 64, 256>>>(h, Wq, bq, Wk, bk);
    round_h_kernel<<<(BATCH * SEQ * EMB) / (4 * 256), 256>>>(h);
    score_kernel<<<dim3(SEQ / 64, SEQ / 64, BATCH), 256>>>();
    colstat_kernel<<<dim3(SEQ / 256, BATCH), 256>>>();
    norm_kernel<<<(BATCH * SEQ * SEQ) / (4 * 256), 256>>>();
    out_gemm_mma_kernel<<<dim3(EMB / 256, SEQ / 128, BATCH), 256, SMEM_TOT>>>(out);
}

// round 4
// speedup vs baseline: 3.7334x; 1.7779x over previous
#include <cuda_runtime.h>
#include <cstdint>

#define BATCH 4
#define SEQ   2048
#define EMB   1024
#define HD    64
#define NQC   16                 // query chunks for colstat partials (2048/128)

// Scratch (allocation-free: __device__ globals)
static __device__ float g_q[BATCH * SEQ * HD];       // 2 MB (tf32-rounded)
static __device__ float g_k[BATCH * SEQ * HD];       // 2 MB (tf32-rounded)
static __device__ float g_s[BATCH * SEQ * SEQ];      // 64 MB: scores -> tf32 weights (in place)
static __device__ float g_hr[BATCH * SEQ * EMB];     // 32 MB: h rounded to tf32
static __device__ float g_wqk[EMB * 128];            // 512 KB: [Wq|Wk] rounded to tf32
static __device__ float g_pm[NQC * BATCH * SEQ];     // partial max
static __device__ float g_pz[NQC * BATCH * SEQ];     // partial sum-exp
static __device__ float g_m[BATCH * SEQ];            // per-(b,key-col) max over q
static __device__ float g_rz[BATCH * SEQ];           // per-(b,key-col) 1/sum(exp)

__device__ __forceinline__ float tf32_rna(float x) {
    uint32_t t;
    asm("cvt.rna.tf32.f32 %0, %1;" : "=r"(t) : "f"(x));
    return __uint_as_float(t);
}
__device__ __forceinline__ void cp_async16(uint32_t saddr, const void* gaddr) {
    asm volatile("cp.async.cg.shared.global [%0], [%1], 16;"
                 :: "r"(saddr), "l"(gaddr) : "memory");
}
__device__ __forceinline__ uint32_t smem_u32(const void* p) {
    uint32_t a;
    asm("{ .reg .u64 t; cvta.to.shared.u64 t, %1; cvt.u32.u64 %0, t; }"
        : "=r"(a) : "l"(p));
    return a;
}
__device__ __forceinline__ void mma_tf32(float* c, const uint32_t* a, const uint32_t* b) {
    asm volatile(
        "mma.sync.aligned.m16n8k8.row.col.f32.tf32.tf32.f32 "
        "{%0,%1,%2,%3}, {%4,%5,%6,%7}, {%8,%9}, {%0,%1,%2,%3};"
        : "+f"(c[0]), "+f"(c[1]), "+f"(c[2]), "+f"(c[3])
        : "r"(a[0]), "r"(a[1]), "r"(a[2]), "r"(a[3]), "r"(b[0]), "r"(b[1]));
}

// ---------------------------------------------------------------------------
// Kernel 0a: g_hr = tf32_round(h)
// ---------------------------------------------------------------------------
__global__ __launch_bounds__(256) void round_h_kernel(const float* __restrict__ h)
{
    const size_t idx = ((size_t)blockIdx.x * 256 + threadIdx.x) * 4;
    float4 v = *(const float4*)(h + idx);
    v.x = tf32_rna(v.x); v.y = tf32_rna(v.y);
    v.z = tf32_rna(v.z); v.w = tf32_rna(v.w);
    *(float4*)(g_hr + idx) = v;
}

// ---------------------------------------------------------------------------
// Kernel 0b: g_wqk[e][0:64] = rna(Wq[e]), g_wqk[e][64:128] = rna(Wk[e])
// ---------------------------------------------------------------------------
__global__ __launch_bounds__(256) void round_w_kernel(
    const float* __restrict__ Wq, const float* __restrict__ Wk)
{
    const int idx = blockIdx.x * 256 + threadIdx.x;   // over EMB*HD = 65536
    const int row = idx >> 6, col = idx & 63;
    g_wqk[row * 128 + col]      = tf32_rna(Wq[idx]);
    g_wqk[row * 128 + 64 + col] = tf32_rna(Wk[idx]);
}

// ---------------------------------------------------------------------------
// Kernel 1: [q|k] = g_hr @ g_wqk + [bq|bk]   via tf32 mma
// CTA tile 128x128, 8 warps (2x4), K-chunk 32, double-buffered cp.async
// ---------------------------------------------------------------------------
#define PA_STR 36
#define PB_STR 136
#define PA_BYTES (128 * PA_STR * 4)   // 18432
#define PB_BYTES (32 * PB_STR * 4)    // 17408
#define PSM_A(p) ((p) * PA_BYTES)
#define PSM_B(p) (2 * PA_BYTES + (p) * PB_BYTES)
#define PSM_TOT  (2 * PA_BYTES + 2 * PB_BYTES)   // 71680

__global__ __launch_bounds__(256) void proj_mma_kernel(
    const float* __restrict__ bq, const float* __restrict__ bk)
{
    extern __shared__ char smem[];
    const uint32_t smem_base = smem_u32(smem);
    const int tid  = threadIdx.x;
    const int wid  = tid >> 5;
    const int lane = tid & 31;
    const int la   = lane >> 2, lb = lane & 3;
    const int wm   = (wid & 1) * 64;
    const int wn   = (wid >> 1) * 32;
    const int m0   = blockIdx.x * 128;
    const float* A = g_hr + (size_t)m0 * EMB;

    float acc[4][4][4];
    #pragma unroll
    for (int i = 0; i < 4; i++)
        #pragma unroll
        for (int j = 0; j < 4; j++)
            #pragma unroll
            for (int q = 0; q < 4; q++) acc[i][j][q] = 0.0f;

    const int am = tid >> 3,  ak = (tid & 7) * 4;
    const int bkr = tid >> 5, bn = (tid & 31) * 4;

    // prologue
    #pragma unroll
    for (int i = 0; i < 4; i++) {
        const int m = am + i * 32;
        cp_async16(smem_base + PSM_A(0) + m * (PA_STR * 4) + ak * 4,
                   A + (size_t)m * EMB + ak);
    }
    #pragma unroll
    for (int i = 0; i < 4; i++) {
        const int k = bkr + i * 8;
        cp_async16(smem_base + PSM_B(0) + k * (PB_STR * 4) + bn * 4,
                   g_wqk + (size_t)k * 128 + bn);
    }
    asm volatile("cp.async.commit_group;" ::: "memory");

    for (int c = 0; c < EMB / 32; ++c) {
        const int p = c & 1;
        if (c < EMB / 32 - 1) {
            const int k0 = (c + 1) * 32;
            #pragma unroll
            for (int i = 0; i < 4; i++) {
                const int m = am + i * 32;
                cp_async16(smem_base + PSM_A(p ^ 1) + m * (PA_STR * 4) + ak * 4,
                           A + (size_t)m * EMB + k0 + ak);
            }
            #pragma unroll
            for (int i = 0; i < 4; i++) {
                const int k = bkr + i * 8;
                cp_async16(smem_base + PSM_B(p ^ 1) + k * (PB_STR * 4) + bn * 4,
                           g_wqk + (size_t)(k0 + k) * 128 + bn);
            }
            asm volatile("cp.async.commit_group;" ::: "memory");
            asm volatile("cp.async.wait_group 1;" ::: "memory");
        } else {
            asm volatile("cp.async.wait_group 0;" ::: "memory");
        }
        __syncthreads();

        const uint32_t* sA = (const uint32_t*)(smem + PSM_A(p));
        const uint32_t* sB = (const uint32_t*)(smem + PSM_B(p));
        #pragma unroll
        for (int kf = 0; kf < 4; kf++) {
            uint32_t afr[4][4];
            #pragma unroll
            for (int mf = 0; mf < 4; mf++) {
                const int r = wm + mf * 16 + la;
                const int cc = kf * 8 + lb;
                afr[mf][0] = sA[r * PA_STR + cc];
                afr[mf][1] = sA[(r + 8) * PA_STR + cc];
                afr[mf][2] = sA[r * PA_STR + cc + 4];
                afr[mf][3] = sA[(r + 8) * PA_STR + cc + 4];
            }
            uint32_t bfr[4][2];
            #pragma unroll
            for (int nf = 0; nf < 4; nf++) {
                const int col = wn + nf * 8 + la;
                const int kk = kf * 8 + lb;
                bfr[nf][0] = sB[kk * PB_STR + col];
                bfr[nf][1] = sB[(kk + 4) * PB_STR + col];
            }
            #pragma unroll
            for (int mf = 0; mf < 4; mf++)
                #pragma unroll
                for (int nf = 0; nf < 4; nf++)
                    mma_tf32(acc[mf][nf], afr[mf], bfr[nf]);
        }
        __syncthreads();
    }

    // epilogue: bias add + tf32 round, split into g_q / g_k
    #pragma unroll
    for (int mf = 0; mf < 4; mf++) {
        const int r0 = m0 + wm + mf * 16 + la;
        #pragma unroll
        for (int nf = 0; nf < 4; nf++) {
            const int cn = wn + nf * 8 + lb * 2;
            float* dst; float b0v, b1v; int cc;
            if (cn < 64) { dst = g_q; cc = cn;      b0v = bq[cc]; b1v = bq[cc + 1]; }
            else         { dst = g_k; cc = cn - 64; b0v = bk[cc]; b1v = bk[cc + 1]; }
            *(float2*)(dst + (size_t)r0 * HD + cc) =
                make_float2(tf32_rna(acc[mf][nf][0] + b0v), tf32_rna(acc[mf][nf][1] + b1v));
            *(float2*)(dst + (size_t)(r0 + 8) * HD + cc) =
                make_float2(tf32_rna(acc[mf][nf][2] + b0v), tf32_rna(acc[mf][nf][3] + b1v));
        }
    }
}

// ---------------------------------------------------------------------------
// Kernel 2: scores = (q @ k^T) * 0.125 via tf32 mma. CTA 128x128, K=64 one-shot.
// ---------------------------------------------------------------------------
#define QS_STR   68
#define QS_BYTES (128 * QS_STR * 4)   // 34816
#define SSM_TOT  (2 * QS_BYTES)       // 69632

__global__ __launch_bounds__(256) void score_mma_kernel()
{
    extern __shared__ char smem[];
    const uint32_t smem_base = smem_u32(smem);
    const int tid  = threadIdx.x;
    const int wid  = tid >> 5;
    const int lane = tid & 31;
    const int la   = lane >> 2, lb = lane & 3;
    const int wm   = (wid & 1) * 64;
    const int wn   = (wid >> 1) * 32;
    const int b    = blockIdx.z;
    const int m0   = blockIdx.y * 128;
    const int n0   = blockIdx.x * 128;
    const float* qg = g_q + ((size_t)b * SEQ + m0) * HD;
    const float* kg = g_k + ((size_t)b * SEQ + n0) * HD;

    const int qr = tid >> 4, qc = (tid & 15) * 4;
    #pragma unroll
    for (int i = 0; i < 8; i++) {
        const int r = qr + i * 16;
        cp_async16(smem_base + r * (QS_STR * 4) + qc * 4, qg + (size_t)r * HD + qc);
        cp_async16(smem_base + QS_BYTES + r * (QS_STR * 4) + qc * 4, kg + (size_t)r * HD + qc);
    }
    asm volatile("cp.async.commit_group;" ::: "memory");
    asm volatile("cp.async.wait_group 0;" ::: "memory");
    __syncthreads();

    const uint32_t* sQ = (const uint32_t*)smem;
    const uint32_t* sK = (const uint32_t*)(smem + QS_BYTES);

    float acc[4][4][4];
    #pragma unroll
    for (int i = 0; i < 4; i++)
        #pragma unroll
        for (int j = 0; j < 4; j++)
            #pragma unroll
            for (int q = 0; q < 4; q++) acc[i][j][q] = 0.0f;

    #pragma unroll
    for (int kf = 0; kf < 8; kf++) {
        uint32_t afr[4][4];
        #pragma unroll
        for (int mf = 0; mf < 4; mf++) {
            const int r = wm + mf * 16 + la;
            const int cc = kf * 8 + lb;
            afr[mf][0] = sQ[r * QS_STR + cc];
            afr[mf][1] = sQ[(r + 8) * QS_STR + cc];
            afr[mf][2] = sQ[r * QS_STR + cc + 4];
            afr[mf][3] = sQ[(r + 8) * QS_STR + cc + 4];
        }
        uint32_t bfr[4][2];
        #pragma unroll
        for (int nf = 0; nf < 4; nf++) {
            const int col = wn + nf * 8 + la;
            const int kk = kf * 8 + lb;
            bfr[nf][0] = sK[col * QS_STR + kk];
            bfr[nf][1] = sK[col * QS_STR + kk + 4];
        }
        #pragma unroll
        for (int mf = 0; mf < 4; mf++)
            #pragma unroll
            for (int nf = 0; nf < 4; nf++)
                mma_tf32(acc[mf][nf], afr[mf], bfr[nf]);
    }

    float* S = g_s + (size_t)b * SEQ * SEQ;
    #pragma unroll
    for (int mf = 0; mf < 4; mf++) {
        const int r0 = m0 + wm + mf * 16 + la;
        #pragma unroll
        for (int nf = 0; nf < 4; nf++) {
            const int cn = n0 + wn + nf * 8 + lb * 2;
            *(float2*)(S + (size_t)r0 * SEQ + cn) =
                make_float2(acc[mf][nf][0] * 0.125f, acc[mf][nf][1] * 0.125f);
            *(float2*)(S + (size_t)(r0 + 8) * SEQ + cn) =
                make_float2(acc[mf][nf][2] * 0.125f, acc[mf][nf][3] * 0.125f);
        }
    }
}

// ---------------------------------------------------------------------------
// Kernel 3a: partial column stats over 128-query chunks (512 CTAs)
// ---------------------------------------------------------------------------
__global__ __launch_bounds__(256) void colstat_part_kernel()
{
    const int b  = blockIdx.z;
    const int qc = blockIdx.y;
    const int col = blockIdx.x * 256 + threadIdx.x;
    const float* p = g_s + (size_t)b * SEQ * SEQ + (size_t)(qc * 128) * SEQ + col;
    float m = -3.0e38f;
    #pragma unroll 8
    for (int i = 0; i < 128; i++) m = fmaxf(m, p[(size_t)i * SEQ]);
    float z = 0.0f;
    #pragma unroll 8
    for (int i = 0; i < 128; i++) z += __expf(p[(size_t)i * SEQ] - m);
    const int idxg = b * SEQ + col;
    g_pm[qc * (BATCH * SEQ) + idxg] = m;
    g_pz[qc * (BATCH * SEQ) + idxg] = z;
}

// ---------------------------------------------------------------------------
// Kernel 3b: merge partials
// ---------------------------------------------------------------------------
__global__ __launch_bounds__(256) void colstat_merge_kernel()
{
    const int idx = blockIdx.x * 256 + threadIdx.x;   // over BATCH*SEQ
    float m = -3.0e38f;
    #pragma unroll
    for (int qc = 0; qc < NQC; qc++) m = fmaxf(m, g_pm[qc * (BATCH * SEQ) + idx]);
    float z = 0.0f;
    #pragma unroll
    for (int qc = 0; qc < NQC; qc++)
        z += g_pz[qc * (BATCH * SEQ) + idx] * __expf(g_pm[qc * (BATCH * SEQ) + idx] - m);
    g_m[idx]  = m;
    g_rz[idx] = 1.0f / z;
}

// ---------------------------------------------------------------------------
// Kernel 4: in-place normalize: w = tf32_round(exp(s - m_col) * rz_col)
// ---------------------------------------------------------------------------
__global__ __launch_bounds__(256) void norm_kernel()
{
    const int idx = (blockIdx.x * 256 + threadIdx.x) * 4;
    const int b = idx >> 22;
    const int k = idx & (SEQ - 1);
    const int base = b * SEQ + k;
    float4 v = *(float4*)(g_s + idx);
    v.x = tf32_rna(__expf(v.x - g_m[base + 0]) * g_rz[base + 0]);
    v.y = tf32_rna(__expf(v.y - g_m[base + 1]) * g_rz[base + 1]);
    v.z = tf32_rna(__expf(v.z - g_m[base + 2]) * g_rz[base + 2]);
    v.w = tf32_rna(__expf(v.w - g_m[base + 3]) * g_rz[base + 3]);
    *(float4*)(g_s + idx) = v;
}

// ---------------------------------------------------------------------------
// Kernel 5: out[b] = W[b] (2048x2048) @ h[b] (2048x1024), tf32 mma.sync.
// ---------------------------------------------------------------------------
#define SA_STRIDE 36
#define SB_STRIDE 264
#define SA_BYTES  (128 * SA_STRIDE * 4)
#define SB_BYTES  (32 * SB_STRIDE * 4)
#define SMEM_A(p) ((p) * SA_BYTES)
#define SMEM_B(p) (2 * SA_BYTES + (p) * SB_BYTES)
#define SMEM_TOT  (2 * SA_BYTES + 2 * SB_BYTES)   // 104448

__global__ __launch_bounds__(256) void out_gemm_mma_kernel(float* __restrict__ out)
{
    extern __shared__ char smem[];
    const uint32_t smem_base = smem_u32(smem);
    const int tid  = threadIdx.x;
    const int wid  = tid >> 5;
    const int lane = tid & 31;
    const int la   = lane >> 2;
    const int lb   = lane & 3;
    const int wm   = (wid & 1) * 64;
    const int wn   = (wid >> 1) * 64;

    const int b  = blockIdx.z;
    const int m0 = blockIdx.y * 128;
    const int n0 = blockIdx.x * 256;
    const float* A = g_s  + (size_t)b * SEQ * SEQ + (size_t)m0 * SEQ;
    const float* B = g_hr + (size_t)b * SEQ * EMB + n0;

    float acc[4][8][4];
    #pragma unroll
    for (int i = 0; i < 4; i++)
        #pragma unroll
        for (int j = 0; j < 8; j++)
            #pragma unroll
            for (int q = 0; q < 4; q++) acc[i][j][q] = 0.0f;

    const int am = tid >> 3;
    const int ak = (tid & 7) * 4;
    const int bk = tid >> 6;
    const int bn = (tid & 63) * 4;

    {
        #pragma unroll
        for (int i = 0; i < 4; i++) {
            const int m = am + i * 32;
            cp_async16(smem_base + SMEM_A(0) + m * (SA_STRIDE * 4) + ak * 4,
                       A + (size_t)m * SEQ + ak);
        }
        #pragma unroll
        for (int i = 0; i < 8; i++) {
            const int k = bk + i * 4;
            cp_async16(smem_base + SMEM_B(0) + k * (SB_STRIDE * 4) + bn * 4,
                       B + (size_t)k * EMB + bn);
        }
        asm volatile("cp.async.commit_group;" ::: "memory");
    }

    for (int c = 0; c < SEQ / 32; ++c) {
        const int p = c & 1;
        if (c < SEQ / 32 - 1) {
            const int k0 = (c + 1) * 32;
            #pragma unroll
            for (int i = 0; i < 4; i++) {
                const int m = am + i * 32;
                cp_async16(smem_base + SMEM_A(p ^ 1) + m * (SA_STRIDE * 4) + ak * 4,
                           A + (size_t)m * SEQ + k0 + ak);
            }
            #pragma unroll
            for (int i = 0; i < 8; i++) {
                const int k = bk + i * 4;
                cp_async16(smem_base + SMEM_B(p ^ 1) + k * (SB_STRIDE * 4) + bn * 4,
                           B + (size_t)(k0 + k) * EMB + bn);
            }
            asm volatile("cp.async.commit_group;" ::: "memory");
            asm volatile("cp.async.wait_group 1;" ::: "memory");
        } else {
            asm volatile("cp.async.wait_group 0;" ::: "memory");
        }
        __syncthreads();

        const uint32_t* sA = (const uint32_t*)(smem + SMEM_A(p));
        const uint32_t* sB = (const uint32_t*)(smem + SMEM_B(p));

        #pragma unroll
        for (int kf = 0; kf < 4; kf++) {
            uint32_t afr[4][4];
            #pragma unroll
            for (int mf = 0; mf < 4; mf++) {
                const int r = wm + mf * 16 + la;
                const int cc = kf * 8 + lb;
                afr[mf][0] = sA[r * SA_STRIDE + cc];
                afr[mf][1] = sA[(r + 8) * SA_STRIDE + cc];
                afr[mf][2] = sA[r * SA_STRIDE + cc + 4];
                afr[mf][3] = sA[(r + 8) * SA_STRIDE + cc + 4];
            }
            uint32_t bfr[8][2];
            #pragma unroll
            for (int nf = 0; nf < 8; nf++) {
                const int col = wn + nf * 8 + la;
                const int kk = kf * 8 + lb;
                bfr[nf][0] = sB[kk * SB_STRIDE + col];
                bfr[nf][1] = sB[(kk + 4) * SB_STRIDE + col];
            }
            #pragma unroll
            for (int mf = 0; mf < 4; mf++)
                #pragma unroll
                for (int nf = 0; nf < 8; nf++)
                    mma_tf32(acc[mf][nf], afr[mf], bfr[nf]);
        }
        __syncthreads();
    }

    float* C = out + (size_t)b * SEQ * EMB;
    #pragma unroll
    for (int mf = 0; mf < 4; mf++) {
        const int r = m0 + wm + mf * 16 + la;
        #pragma unroll
        for (int nf = 0; nf < 8; nf++) {
            const int col = n0 + wn + nf * 8 + lb * 2;
            *(float2*)(C + (size_t)r * EMB + col)       = make_float2(acc[mf][nf][0], acc[mf][nf][1]);
            *(float2*)(C + (size_t)(r + 8) * EMB + col) = make_float2(acc[mf][nf][2], acc[mf][nf][3]);
        }
    }
}

// ---------------------------------------------------------------------------
extern "C" void kernel_launch(void* const* d_in, const int* in_sizes, int n_in,
                              void* d_out, int out_size)
{
    const float* h  = (const float*)d_in[0];
    const float* Wq = (const float*)d_in[1];
    const float* bq = (const float*)d_in[2];
    const float* Wk = (const float*)d_in[3];
    const float* bk = (const float*)d_in[4];
    float* out = (float*)d_out;

    static int smem_set = 0;
    if (!smem_set) {
        cudaFuncSetAttribute(out_gemm_mma_kernel,
                             cudaFuncAttributeMaxDynamicSharedMemorySize, SMEM_TOT);
        cudaFuncSetAttribute(proj_mma_kernel,
                             cudaFuncAttributeMaxDynamicSharedMemorySize, PSM_TOT);
        cudaFuncSetAttribute(score_mma_kernel,
                             cudaFuncAttributeMaxDynamicSharedMemorySize, SSM_TOT);
        smem_set = 1;
    }

    round_h_kernel<<<(BATCH * SEQ * EMB) / (4 * 256), 256>>>(h);
    round_w_kernel<<<(EMB * HD) / 256, 256>>>(Wq, Wk);
    proj_mma_kernel<<<(BATCH * SEQ) / 128, 256, PSM_TOT>>>(bq, bk);
    score_mma_kernel<<<dim3(SEQ / 128, SEQ / 128, BATCH), 256, SSM_TOT>>>();
    colstat_part_kernel<<<dim3(SEQ / 256, NQC, BATCH), 256>>>();
    colstat_merge_kernel<<<(BATCH * SEQ) / 256, 256>>>();
    norm_kernel<<<(BATCH * SEQ * SEQ) / (4 * 256), 256>>>();
    out_gemm_mma_kernel<<<dim3(EMB / 256, SEQ / 128, BATCH), 256, SMEM_TOT>>>(out);
}

// round 5
// speedup vs baseline: 5.0418x; 1.3505x over previous
#include <cuda_runtime.h>
#include <cuda_fp16.h>
#include <cstdint>

#define BATCH 4
#define SEQ   2048
#define EMB   1024
#define HD    64
#define NQC   16                 // query chunks for colstat partials

// Scratch (allocation-free: __device__ globals)
static __device__ float  g_q[BATCH * SEQ * HD];       // 2 MB (tf32-rounded)
static __device__ float  g_k[BATCH * SEQ * HD];       // 2 MB (tf32-rounded)
static __device__ float  g_s[BATCH * SEQ * SEQ];      // 64 MB: fp32 scores
static __device__ __half g_wh[BATCH * SEQ * SEQ];     // 32 MB: fp16 softmax weights
static __device__ float  g_hr[BATCH * SEQ * EMB];     // 32 MB: h rounded to tf32
static __device__ __half g_hht[BATCH * EMB * SEQ];    // 16 MB: h fp16, transposed [B][E][S]
static __device__ float  g_wqk[EMB * 128];            // [Wq|Wk] tf32
static __device__ float  g_pm[NQC * BATCH * SEQ];
static __device__ float  g_pz[NQC * BATCH * SEQ];
static __device__ float  g_m[BATCH * SEQ];
static __device__ float  g_rz[BATCH * SEQ];

__device__ __forceinline__ float tf32_rna(float x) {
    uint32_t t;
    asm("cvt.rna.tf32.f32 %0, %1;" : "=r"(t) : "f"(x));
    return __uint_as_float(t);
}
__device__ __forceinline__ void cp_async16(uint32_t saddr, const void* gaddr) {
    asm volatile("cp.async.cg.shared.global [%0], [%1], 16;"
                 :: "r"(saddr), "l"(gaddr) : "memory");
}
__device__ __forceinline__ uint32_t smem_u32(const void* p) {
    uint32_t a;
    asm("{ .reg .u64 t; cvta.to.shared.u64 t, %1; cvt.u32.u64 %0, t; }"
        : "=r"(a) : "l"(p));
    return a;
}
__device__ __forceinline__ void mma_tf32(float* c, const uint32_t* a, const uint32_t* b) {
    asm volatile(
        "mma.sync.aligned.m16n8k8.row.col.f32.tf32.tf32.f32 "
        "{%0,%1,%2,%3}, {%4,%5,%6,%7}, {%8,%9}, {%0,%1,%2,%3};"
        : "+f"(c[0]), "+f"(c[1]), "+f"(c[2]), "+f"(c[3])
        : "r"(a[0]), "r"(a[1]), "r"(a[2]), "r"(a[3]), "r"(b[0]), "r"(b[1]));
}
__device__ __forceinline__ void mma_f16(float* c, const uint32_t* a, const uint32_t* b) {
    asm volatile(
        "mma.sync.aligned.m16n8k16.row.col.f32.f16.f16.f32 "
        "{%0,%1,%2,%3}, {%4,%5,%6,%7}, {%8,%9}, {%0,%1,%2,%3};"
        : "+f"(c[0]), "+f"(c[1]), "+f"(c[2]), "+f"(c[3])
        : "r"(a[0]), "r"(a[1]), "r"(a[2]), "r"(a[3]), "r"(b[0]), "r"(b[1]));
}

// ---------------------------------------------------------------------------
// Kernel 0a: g_hr = tf32_round(h)
// ---------------------------------------------------------------------------
__global__ __launch_bounds__(256) void round_h_kernel(const float* __restrict__ h)
{
    const size_t idx = ((size_t)blockIdx.x * 256 + threadIdx.x) * 4;
    float4 v = *(const float4*)(h + idx);
    v.x = tf32_rna(v.x); v.y = tf32_rna(v.y);
    v.z = tf32_rna(v.z); v.w = tf32_rna(v.w);
    *(float4*)(g_hr + idx) = v;
}

// ---------------------------------------------------------------------------
// Kernel 0b: g_wqk = [rna(Wq) | rna(Wk)]
// ---------------------------------------------------------------------------
__global__ __launch_bounds__(256) void round_w_kernel(
    const float* __restrict__ Wq, const float* __restrict__ Wk)
{
    const int idx = blockIdx.x * 256 + threadIdx.x;
    const int row = idx >> 6, col = idx & 63;
    g_wqk[row * 128 + col]      = tf32_rna(Wq[idx]);
    g_wqk[row * 128 + 64 + col] = tf32_rna(Wk[idx]);
}

// ---------------------------------------------------------------------------
// Kernel 0c: g_hht[b][e][s] = fp16(h[b][s][e])  (transpose + convert)
// ---------------------------------------------------------------------------
__global__ void conv_ht_kernel(const float* __restrict__ h)
{
    __shared__ float tile[32][33];
    const int b = blockIdx.z;
    const int s0 = blockIdx.x * 32;
    const int e0 = blockIdx.y * 32;
    const int tx = threadIdx.x, ty = threadIdx.y;
    const float* src = h + ((size_t)b * SEQ + s0) * EMB + e0;
    #pragma unroll
    for (int r = ty; r < 32; r += 8)
        tile[r][tx] = src[(size_t)r * EMB + tx];
    __syncthreads();
    __half* dst = g_hht + ((size_t)b * EMB + e0) * SEQ + s0;
    #pragma unroll
    for (int r = ty; r < 32; r += 8)
        dst[(size_t)r * SEQ + tx] = __float2half(tile[tx][r]);
}

// ---------------------------------------------------------------------------
// Kernel 1: [q|k] = g_hr @ g_wqk + [bq|bk]   via tf32 mma (CTA 128x128)
// ---------------------------------------------------------------------------
#define PA_STR 36
#define PB_STR 136
#define PA_BYTES (128 * PA_STR * 4)
#define PB_BYTES (32 * PB_STR * 4)
#define PSM_A(p) ((p) * PA_BYTES)
#define PSM_B(p) (2 * PA_BYTES + (p) * PB_BYTES)
#define PSM_TOT  (2 * PA_BYTES + 2 * PB_BYTES)

__global__ __launch_bounds__(256) void proj_mma_kernel(
    const float* __restrict__ bq, const float* __restrict__ bk)
{
    extern __shared__ char smem[];
    const uint32_t smem_base = smem_u32(smem);
    const int tid  = threadIdx.x;
    const int wid  = tid >> 5;
    const int lane = tid & 31;
    const int la   = lane >> 2, lb = lane & 3;
    const int wm   = (wid & 1) * 64;
    const int wn   = (wid >> 1) * 32;
    const int m0   = blockIdx.x * 128;
    const float* A = g_hr + (size_t)m0 * EMB;

    float acc[4][4][4];
    #pragma unroll
    for (int i = 0; i < 4; i++)
        #pragma unroll
        for (int j = 0; j < 4; j++)
            #pragma unroll
            for (int q = 0; q < 4; q++) acc[i][j][q] = 0.0f;

    const int am = tid >> 3,  ak = (tid & 7) * 4;
    const int bkr = tid >> 5, bn = (tid & 31) * 4;

    #pragma unroll
    for (int i = 0; i < 4; i++) {
        const int m = am + i * 32;
        cp_async16(smem_base + PSM_A(0) + m * (PA_STR * 4) + ak * 4,
                   A + (size_t)m * EMB + ak);
    }
    #pragma unroll
    for (int i = 0; i < 4; i++) {
        const int k = bkr + i * 8;
        cp_async16(smem_base + PSM_B(0) + k * (PB_STR * 4) + bn * 4,
                   g_wqk + (size_t)k * 128 + bn);
    }
    asm volatile("cp.async.commit_group;" ::: "memory");

    for (int c = 0; c < EMB / 32; ++c) {
        const int p = c & 1;
        if (c < EMB / 32 - 1) {
            const int k0 = (c + 1) * 32;
            #pragma unroll
            for (int i = 0; i < 4; i++) {
                const int m = am + i * 32;
                cp_async16(smem_base + PSM_A(p ^ 1) + m * (PA_STR * 4) + ak * 4,
                           A + (size_t)m * EMB + k0 + ak);
            }
            #pragma unroll
            for (int i = 0; i < 4; i++) {
                const int k = bkr + i * 8;
                cp_async16(smem_base + PSM_B(p ^ 1) + k * (PB_STR * 4) + bn * 4,
                           g_wqk + (size_t)(k0 + k) * 128 + bn);
            }
            asm volatile("cp.async.commit_group;" ::: "memory");
            asm volatile("cp.async.wait_group 1;" ::: "memory");
        } else {
            asm volatile("cp.async.wait_group 0;" ::: "memory");
        }
        __syncthreads();

        const uint32_t* sA = (const uint32_t*)(smem + PSM_A(p));
        const uint32_t* sB = (const uint32_t*)(smem + PSM_B(p));
        #pragma unroll
        for (int kf = 0; kf < 4; kf++) {
            uint32_t afr[4][4];
            #pragma unroll
            for (int mf = 0; mf < 4; mf++) {
                const int r = wm + mf * 16 + la;
                const int cc = kf * 8 + lb;
                afr[mf][0] = sA[r * PA_STR + cc];
                afr[mf][1] = sA[(r + 8) * PA_STR + cc];
                afr[mf][2] = sA[r * PA_STR + cc + 4];
                afr[mf][3] = sA[(r + 8) * PA_STR + cc + 4];
            }
            uint32_t bfr[4][2];
            #pragma unroll
            for (int nf = 0; nf < 4; nf++) {
                const int col = wn + nf * 8 + la;
                const int kk = kf * 8 + lb;
                bfr[nf][0] = sB[kk * PB_STR + col];
                bfr[nf][1] = sB[(kk + 4) * PB_STR + col];
            }
            #pragma unroll
            for (int mf = 0; mf < 4; mf++)
                #pragma unroll
                for (int nf = 0; nf < 4; nf++)
                    mma_tf32(acc[mf][nf], afr[mf], bfr[nf]);
        }
        __syncthreads();
    }

    #pragma unroll
    for (int mf = 0; mf < 4; mf++) {
        const int r0 = m0 + wm + mf * 16 + la;
        #pragma unroll
        for (int nf = 0; nf < 4; nf++) {
            const int cn = wn + nf * 8 + lb * 2;
            float* dst; float b0v, b1v; int cc;
            if (cn < 64) { dst = g_q; cc = cn;      b0v = bq[cc]; b1v = bq[cc + 1]; }
            else         { dst = g_k; cc = cn - 64; b0v = bk[cc]; b1v = bk[cc + 1]; }
            *(float2*)(dst + (size_t)r0 * HD + cc) =
                make_float2(tf32_rna(acc[mf][nf][0] + b0v), tf32_rna(acc[mf][nf][1] + b1v));
            *(float2*)(dst + (size_t)(r0 + 8) * HD + cc) =
                make_float2(tf32_rna(acc[mf][nf][2] + b0v), tf32_rna(acc[mf][nf][3] + b1v));
        }
    }
}

// ---------------------------------------------------------------------------
// Kernel 2: scores = (q @ k^T) * 0.125 via tf32 mma. CTA 128x128, K=64.
// ---------------------------------------------------------------------------
#define QS_STR   68
#define QS_BYTES (128 * QS_STR * 4)
#define SSM_TOT  (2 * QS_BYTES)

__global__ __launch_bounds__(256) void score_mma_kernel()
{
    extern __shared__ char smem[];
    const uint32_t smem_base = smem_u32(smem);
    const int tid  = threadIdx.x;
    const int wid  = tid >> 5;
    const int lane = tid & 31;
    const int la   = lane >> 2, lb = lane & 3;
    const int wm   = (wid & 1) * 64;
    const int wn   = (wid >> 1) * 32;
    const int b    = blockIdx.z;
    const int m0   = blockIdx.y * 128;
    const int n0   = blockIdx.x * 128;
    const float* qg = g_q + ((size_t)b * SEQ + m0) * HD;
    const float* kg = g_k + ((size_t)b * SEQ + n0) * HD;

    const int qr = tid >> 4, qc = (tid & 15) * 4;
    #pragma unroll
    for (int i = 0; i < 8; i++) {
        const int r = qr + i * 16;
        cp_async16(smem_base + r * (QS_STR * 4) + qc * 4, qg + (size_t)r * HD + qc);
        cp_async16(smem_base + QS_BYTES + r * (QS_STR * 4) + qc * 4, kg + (size_t)r * HD + qc);
    }
    asm volatile("cp.async.commit_group;" ::: "memory");
    asm volatile("cp.async.wait_group 0;" ::: "memory");
    __syncthreads();

    const uint32_t* sQ = (const uint32_t*)smem;
    const uint32_t* sK = (const uint32_t*)(smem + QS_BYTES);

    float acc[4][4][4];
    #pragma unroll
    for (int i = 0; i < 4; i++)
        #pragma unroll
        for (int j = 0; j < 4; j++)
            #pragma unroll
            for (int q = 0; q < 4; q++) acc[i][j][q] = 0.0f;

    #pragma unroll
    for (int kf = 0; kf < 8; kf++) {
        uint32_t afr[4][4];
        #pragma unroll
        for (int mf = 0; mf < 4; mf++) {
            const int r = wm + mf * 16 + la;
            const int cc = kf * 8 + lb;
            afr[mf][0] = sQ[r * QS_STR + cc];
            afr[mf][1] = sQ[(r + 8) * QS_STR + cc];
            afr[mf][2] = sQ[r * QS_STR + cc + 4];
            afr[mf][3] = sQ[(r + 8) * QS_STR + cc + 4];
        }
        uint32_t bfr[4][2];
        #pragma unroll
        for (int nf = 0; nf < 4; nf++) {
            const int col = wn + nf * 8 + la;
            const int kk = kf * 8 + lb;
            bfr[nf][0] = sK[col * QS_STR + kk];
            bfr[nf][1] = sK[col * QS_STR + kk + 4];
        }
        #pragma unroll
        for (int mf = 0; mf < 4; mf++)
            #pragma unroll
            for (int nf = 0; nf < 4; nf++)
                mma_tf32(acc[mf][nf], afr[mf], bfr[nf]);
    }

    float* S = g_s + (size_t)b * SEQ * SEQ;
    #pragma unroll
    for (int mf = 0; mf < 4; mf++) {
        const int r0 = m0 + wm + mf * 16 + la;
        #pragma unroll
        for (int nf = 0; nf < 4; nf++) {
            const int cn = n0 + wn + nf * 8 + lb * 2;
            *(float2*)(S + (size_t)r0 * SEQ + cn) =
                make_float2(acc[mf][nf][0] * 0.125f, acc[mf][nf][1] * 0.125f);
            *(float2*)(S + (size_t)(r0 + 8) * SEQ + cn) =
                make_float2(acc[mf][nf][2] * 0.125f, acc[mf][nf][3] * 0.125f);
        }
    }
}

// ---------------------------------------------------------------------------
// Kernel 3a: partial column stats over 128-query chunks
// ---------------------------------------------------------------------------
__global__ __launch_bounds__(256) void colstat_part_kernel()
{
    const int b  = blockIdx.z;
    const int qc = blockIdx.y;
    const int col = blockIdx.x * 256 + threadIdx.x;
    const float* p = g_s + (size_t)b * SEQ * SEQ + (size_t)(qc * 128) * SEQ + col;
    float m = -3.0e38f;
    #pragma unroll 8
    for (int i = 0; i < 128; i++) m = fmaxf(m, p[(size_t)i * SEQ]);
    float z = 0.0f;
    #pragma unroll 8
    for (int i = 0; i < 128; i++) z += __expf(p[(size_t)i * SEQ] - m);
    const int idxg = b * SEQ + col;
    g_pm[qc * (BATCH * SEQ) + idxg] = m;
    g_pz[qc * (BATCH * SEQ) + idxg] = z;
}

// ---------------------------------------------------------------------------
// Kernel 3b: merge partials
// ---------------------------------------------------------------------------
__global__ __launch_bounds__(256) void colstat_merge_kernel()
{
    const int idx = blockIdx.x * 256 + threadIdx.x;
    float m = -3.0e38f;
    #pragma unroll
    for (int qc = 0; qc < NQC; qc++) m = fmaxf(m, g_pm[qc * (BATCH * SEQ) + idx]);
    float z = 0.0f;
    #pragma unroll
    for (int qc = 0; qc < NQC; qc++)
        z += g_pz[qc * (BATCH * SEQ) + idx] * __expf(g_pm[qc * (BATCH * SEQ) + idx] - m);
    g_m[idx]  = m;
    g_rz[idx] = 1.0f / z;
}

// ---------------------------------------------------------------------------
// Kernel 4: normalize: g_wh = fp16(exp(s - m_col) * rz_col)
// ---------------------------------------------------------------------------
__global__ __launch_bounds__(256) void norm_kernel()
{
    const int idx = (blockIdx.x * 256 + threadIdx.x) * 4;
    const int b = idx >> 22;
    const int k = idx & (SEQ - 1);
    const int base = b * SEQ + k;
    float4 v = *(const float4*)(g_s + idx);
    float w0 = __expf(v.x - g_m[base + 0]) * g_rz[base + 0];
    float w1 = __expf(v.y - g_m[base + 1]) * g_rz[base + 1];
    float w2 = __expf(v.z - g_m[base + 2]) * g_rz[base + 2];
    float w3 = __expf(v.w - g_m[base + 3]) * g_rz[base + 3];
    __half2 h0 = __floats2half2_rn(w0, w1);
    __half2 h1 = __floats2half2_rn(w2, w3);
    *(uint2*)(g_wh + idx) = make_uint2(*(uint32_t*)&h0, *(uint32_t*)&h1);
}

// ---------------------------------------------------------------------------
// Kernel 5: out[b] = W[b] @ h[b] via fp16 mma (m16n8k16).
// CTA 128x256, K-chunk 64, 8 warps (2x4), warp tile 64x64, double buffer.
// A smem [128][72] halves, B smem [256][72] halves (B pre-transposed [n][k]).
// ---------------------------------------------------------------------------
#define OA_STR   72                          // halves (144B rows)
#define OA_BYTES (128 * OA_STR * 2)          // 18432
#define OB_BYTES (256 * OA_STR * 2)          // 36864
#define OSM_A(p) ((p) * (OA_BYTES + OB_BYTES))
#define OSM_B(p) (OSM_A(p) + OA_BYTES)
#define OSM_TOT  (2 * (OA_BYTES + OB_BYTES)) // 110592

__global__ __launch_bounds__(256) void out_gemm_f16_kernel(float* __restrict__ out)
{
    extern __shared__ char smem[];
    const uint32_t smem_base = smem_u32(smem);
    const int tid  = threadIdx.x;
    const int wid  = tid >> 5;
    const int lane = tid & 31;
    const int la   = lane >> 2;
    const int lb   = lane & 3;
    const int wm   = (wid & 1) * 64;
    const int wn   = (wid >> 1) * 64;

    const int b  = blockIdx.z;
    const int m0 = blockIdx.y * 128;
    const int n0 = blockIdx.x * 256;
    const __half* A  = g_wh  + (size_t)b * SEQ * SEQ + (size_t)m0 * SEQ;  // [128 rows][k]
    const __half* Bt = g_hht + (size_t)b * EMB * SEQ + (size_t)n0 * SEQ;  // [256 rows n][k]

    float acc[4][8][4];
    #pragma unroll
    for (int i = 0; i < 4; i++)
        #pragma unroll
        for (int j = 0; j < 8; j++)
            #pragma unroll
            for (int q = 0; q < 4; q++) acc[i][j][q] = 0.0f;

    // prologue: chunk 0
    #pragma unroll
    for (int i = 0; i < 4; i++) {
        const int idx = tid + i * 256;
        const int row = idx >> 3, ch = idx & 7;
        cp_async16(smem_base + OSM_A(0) + row * 144 + ch * 16,
                   A + (size_t)row * SEQ + ch * 8);
    }
    #pragma unroll
    for (int i = 0; i < 8; i++) {
        const int idx = tid + i * 256;
        const int row = idx >> 3, ch = idx & 7;
        cp_async16(smem_base + OSM_B(0) + row * 144 + ch * 16,
                   Bt + (size_t)row * SEQ + ch * 8);
    }
    asm volatile("cp.async.commit_group;" ::: "memory");

    for (int c = 0; c < SEQ / 64; ++c) {
        const int p = c & 1;
        if (c < SEQ / 64 - 1) {
            const int k0 = (c + 1) * 64;
            #pragma unroll
            for (int i = 0; i < 4; i++) {
                const int idx = tid + i * 256;
                const int row = idx >> 3, ch = idx & 7;
                cp_async16(smem_base + OSM_A(p ^ 1) + row * 144 + ch * 16,
                           A + (size_t)row * SEQ + k0 + ch * 8);
            }
            #pragma unroll
            for (int i = 0; i < 8; i++) {
                const int idx = tid + i * 256;
                const int row = idx >> 3, ch = idx & 7;
                cp_async16(smem_base + OSM_B(p ^ 1) + row * 144 + ch * 16,
                           Bt + (size_t)row * SEQ + k0 + ch * 8);
            }
            asm volatile("cp.async.commit_group;" ::: "memory");
            asm volatile("cp.async.wait_group 1;" ::: "memory");
        } else {
            asm volatile("cp.async.wait_group 0;" ::: "memory");
        }
        __syncthreads();

        const uint32_t* sA = (const uint32_t*)(smem + OSM_A(p));   // word stride 36
        const uint32_t* sB = (const uint32_t*)(smem + OSM_B(p));

        #pragma unroll
        for (int kf = 0; kf < 4; kf++) {
            uint32_t afr[4][4];
            #pragma unroll
            for (int mf = 0; mf < 4; mf++) {
                const int r = wm + mf * 16 + la;
                const int base = r * 36 + kf * 8 + lb;
                afr[mf][0] = sA[base];
                afr[mf][1] = sA[base + 8 * 36];
                afr[mf][2] = sA[base + 4];
                afr[mf][3] = sA[base + 8 * 36 + 4];
            }
            uint32_t bfr[8][2];
            #pragma unroll
            for (int nf = 0; nf < 8; nf++) {
                const int n = wn + nf * 8 + la;
                const int base = n * 36 + kf * 8 + lb;
                bfr[nf][0] = sB[base];
                bfr[nf][1] = sB[base + 4];
            }
            #pragma unroll
            for (int mf = 0; mf < 4; mf++)
                #pragma unroll
                for (int nf = 0; nf < 8; nf++)
                    mma_f16(acc[mf][nf], afr[mf], bfr[nf]);
        }
        __syncthreads();
    }

    float* C = out + (size_t)b * SEQ * EMB;
    #pragma unroll
    for (int mf = 0; mf < 4; mf++) {
        const int r = m0 + wm + mf * 16 + la;
        #pragma unroll
        for (int nf = 0; nf < 8; nf++) {
            const int col = n0 + wn + nf * 8 + lb * 2;
            *(float2*)(C + (size_t)r * EMB + col)       = make_float2(acc[mf][nf][0], acc[mf][nf][1]);
            *(float2*)(C + (size_t)(r + 8) * EMB + col) = make_float2(acc[mf][nf][2], acc[mf][nf][3]);
        }
    }
}

// ---------------------------------------------------------------------------
extern "C" void kernel_launch(void* const* d_in, const int* in_sizes, int n_in,
                              void* d_out, int out_size)
{
    const float* h  = (const float*)d_in[0];
    const float* Wq = (const float*)d_in[1];
    const float* bq = (const float*)d_in[2];
    const float* Wk = (const float*)d_in[3];
    const float* bk = (const float*)d_in[4];
    float* out = (float*)d_out;

    static int smem_set = 0;
    if (!smem_set) {
        cudaFuncSetAttribute(out_gemm_f16_kernel,
                             cudaFuncAttributeMaxDynamicSharedMemorySize, OSM_TOT);
        cudaFuncSetAttribute(proj_mma_kernel,
                             cudaFuncAttributeMaxDynamicSharedMemorySize, PSM_TOT);
        cudaFuncSetAttribute(score_mma_kernel,
                             cudaFuncAttributeMaxDynamicSharedMemorySize, SSM_TOT);
        smem_set = 1;
    }

    round_h_kernel<<<(BATCH * SEQ * EMB) / (4 * 256), 256>>>(h);
    round_w_kernel<<<(EMB * HD) / 256, 256>>>(Wq, Wk);
    conv_ht_kernel<<<dim3(SEQ / 32, EMB / 32, BATCH), dim3(32, 8)>>>(h);
    proj_mma_kernel<<<(BATCH * SEQ) / 128, 256, PSM_TOT>>>(bq, bk);
    score_mma_kernel<<<dim3(SEQ / 128, SEQ / 128, BATCH), 256, SSM_TOT>>>();
    colstat_part_kernel<<<dim3(SEQ / 256, NQC, BATCH), 256>>>();
    colstat_merge_kernel<<<(BATCH * SEQ) / 256, 256>>>();
    norm_kernel<<<(BATCH * SEQ * SEQ) / (4 * 256), 256>>>();
    out_gemm_f16_kernel<<<dim3(EMB / 256, SEQ / 128, BATCH), 256, OSM_TOT>>>(out);
}

// round 6
// speedup vs baseline: 5.9451x; 1.1792x over previous
#include <cuda_runtime.h>
#include <cuda_fp16.h>
#include <cstdint>

#define BATCH 4
#define SEQ   2048
#define EMB   1024
#define HD    64
#define NQC   16                 // query chunks (SEQ/128) for colstat partials

// Scratch (allocation-free: __device__ globals)
static __device__ float  g_s[BATCH * SEQ * SEQ];      // 64 MB fp32 scores
static __device__ __half g_wh[BATCH * SEQ * SEQ];     // 32 MB fp16 softmax weights
static __device__ __half g_hh[BATCH * SEQ * EMB];     // 16 MB fp16 h row-major
static __device__ __half g_hht[BATCH * EMB * SEQ];    // 16 MB fp16 h transposed [B][E][S]
static __device__ __half g_qh[BATCH * SEQ * HD];      // 1 MB fp16 q
static __device__ __half g_kh[BATCH * SEQ * HD];      // 1 MB fp16 k
static __device__ __half g_wqkt[128 * EMB];           // 256 KB fp16 [Wq|Wk]^T : [n][e]
static __device__ float  g_pm[NQC * BATCH * SEQ];
static __device__ float  g_pz[NQC * BATCH * SEQ];
static __device__ float  g_m[BATCH * SEQ];
static __device__ float  g_rz[BATCH * SEQ];

__device__ __forceinline__ void cp_async16(uint32_t saddr, const void* gaddr) {
    asm volatile("cp.async.cg.shared.global [%0], [%1], 16;"
                 :: "r"(saddr), "l"(gaddr) : "memory");
}
__device__ __forceinline__ uint32_t smem_u32(const void* p) {
    uint32_t a;
    asm("{ .reg .u64 t; cvta.to.shared.u64 t, %1; cvt.u32.u64 %0, t; }"
        : "=r"(a) : "l"(p));
    return a;
}
__device__ __forceinline__ void mma_f16(float* c, const uint32_t* a, const uint32_t* b) {
    asm volatile(
        "mma.sync.aligned.m16n8k16.row.col.f32.f16.f16.f32 "
        "{%0,%1,%2,%3}, {%4,%5,%6,%7}, {%8,%9}, {%0,%1,%2,%3};"
        : "+f"(c[0]), "+f"(c[1]), "+f"(c[2]), "+f"(c[3])
        : "r"(a[0]), "r"(a[1]), "r"(a[2]), "r"(a[3]), "r"(b[0]), "r"(b[1]));
}

// ---------------------------------------------------------------------------
// Kernel 0a: h -> g_hh (fp16 row-major) and g_hht (fp16 transposed)
// ---------------------------------------------------------------------------
__global__ void conv_h_kernel(const float* __restrict__ h)
{
    __shared__ float tile[32][33];
    const int b = blockIdx.z;
    const int s0 = blockIdx.x * 32;
    const int e0 = blockIdx.y * 32;
    const int tx = threadIdx.x, ty = threadIdx.y;
    const float* src = h + ((size_t)b * SEQ + s0) * EMB + e0;
    #pragma unroll
    for (int r = ty; r < 32; r += 8) {
        float v = src[(size_t)r * EMB + tx];
        tile[r][tx] = v;
        g_hh[((size_t)b * SEQ + s0 + r) * EMB + e0 + tx] = __float2half(v);
    }
    __syncthreads();
    __half* dst = g_hht + ((size_t)b * EMB + e0) * SEQ + s0;
    #pragma unroll
    for (int r = ty; r < 32; r += 8)
        dst[(size_t)r * SEQ + tx] = __float2half(tile[tx][r]);
}

// ---------------------------------------------------------------------------
// Kernel 0b: g_wqkt[n][e] = fp16( n<64 ? Wq[e][n] : Wk[e][n-64] )
// ---------------------------------------------------------------------------
__global__ __launch_bounds__(256) void conv_w_kernel(
    const float* __restrict__ Wq, const float* __restrict__ Wk)
{
    const int col = blockIdx.x;                  // 0..127
    const float* W = (col < 64) ? Wq : Wk;
    const int c = col & 63;
    for (int e = threadIdx.x; e < EMB; e += 256)
        g_wqkt[col * EMB + e] = __float2half(W[(size_t)e * HD + c]);
}

// ---------------------------------------------------------------------------
// Kernel 1: [q|k] = g_hh @ [Wq|Wk] + [bq|bk]  via fp16 mma (m16n8k16).
// CTA tile M=64 x N=128, grid = 8192/64 = 128. K-chunk 64, double buffer.
// ---------------------------------------------------------------------------
#define PJA_BYTES (64 * 144)                 // 64 rows x 72 halves
#define PJB_BYTES (128 * 144)
#define PJ_STAGE  (PJA_BYTES + PJB_BYTES)    // 27648
#define PJ_TOT    (2 * PJ_STAGE)             // 55296

__global__ __launch_bounds__(256) void proj_f16_kernel(
    const float* __restrict__ bq, const float* __restrict__ bk)
{
    extern __shared__ char smem[];
    const uint32_t smem_base = smem_u32(smem);
    const int tid  = threadIdx.x;
    const int wid  = tid >> 5;
    const int lane = tid & 31;
    const int la   = lane >> 2, lb = lane & 3;
    const int wm   = (wid & 1) * 32;
    const int wn   = (wid >> 1) * 32;
    const int m0   = blockIdx.x * 64;
    const __half* A = g_hh + (size_t)m0 * EMB;

    float acc[2][4][4];
    #pragma unroll
    for (int i = 0; i < 2; i++)
        #pragma unroll
        for (int j = 0; j < 4; j++)
            #pragma unroll
            for (int q = 0; q < 4; q++) acc[i][j][q] = 0.0f;

    // prologue chunk 0
    #pragma unroll
    for (int i = 0; i < 2; i++) {
        const int idx = tid + i * 256;
        const int row = idx >> 3, ch = idx & 7;
        cp_async16(smem_base + row * 144 + ch * 16, A + (size_t)row * EMB + ch * 8);
    }
    #pragma unroll
    for (int i = 0; i < 4; i++) {
        const int idx = tid + i * 256;
        const int row = idx >> 3, ch = idx & 7;
        cp_async16(smem_base + PJA_BYTES + row * 144 + ch * 16,
                   g_wqkt + (size_t)row * EMB + ch * 8);
    }
    asm volatile("cp.async.commit_group;" ::: "memory");

    for (int c = 0; c < EMB / 64; ++c) {
        const int p = c & 1;
        if (c < EMB / 64 - 1) {
            const int k0 = (c + 1) * 64;
            const uint32_t st = smem_base + (p ^ 1) * PJ_STAGE;
            #pragma unroll
            for (int i = 0; i < 2; i++) {
                const int idx = tid + i * 256;
                const int row = idx >> 3, ch = idx & 7;
                cp_async16(st + row * 144 + ch * 16, A + (size_t)row * EMB + k0 + ch * 8);
            }
            #pragma unroll
            for (int i = 0; i < 4; i++) {
                const int idx = tid + i * 256;
                const int row = idx >> 3, ch = idx & 7;
                cp_async16(st + PJA_BYTES + row * 144 + ch * 16,
                           g_wqkt + (size_t)row * EMB + k0 + ch * 8);
            }
            asm volatile("cp.async.commit_group;" ::: "memory");
            asm volatile("cp.async.wait_group 1;" ::: "memory");
        } else {
            asm volatile("cp.async.wait_group 0;" ::: "memory");
        }
        __syncthreads();

        const uint32_t* sA = (const uint32_t*)(smem + p * PJ_STAGE);           // stride 36 words
        const uint32_t* sB = (const uint32_t*)(smem + p * PJ_STAGE + PJA_BYTES);

        #pragma unroll
        for (int kf = 0; kf < 4; kf++) {
            uint32_t afr[2][4];
            #pragma unroll
            for (int mf = 0; mf < 2; mf++) {
                const int r = wm + mf * 16 + la;
                const int base = r * 36 + kf * 8 + lb;
                afr[mf][0] = sA[base];
                afr[mf][1] = sA[base + 8 * 36];
                afr[mf][2] = sA[base + 4];
                afr[mf][3] = sA[base + 8 * 36 + 4];
            }
            uint32_t bfr[4][2];
            #pragma unroll
            for (int nf = 0; nf < 4; nf++) {
                const int n = wn + nf * 8 + la;
                const int base = n * 36 + kf * 8 + lb;
                bfr[nf][0] = sB[base];
                bfr[nf][1] = sB[base + 4];
            }
            #pragma unroll
            for (int mf = 0; mf < 2; mf++)
                #pragma unroll
                for (int nf = 0; nf < 4; nf++)
                    mma_f16(acc[mf][nf], afr[mf], bfr[nf]);
        }
        __syncthreads();
    }

    // epilogue: bias add, cvt fp16, split q/k
    #pragma unroll
    for (int mf = 0; mf < 2; mf++) {
        const int r0 = m0 + wm + mf * 16 + la;
        #pragma unroll
        for (int nf = 0; nf < 4; nf++) {
            const int cn = wn + nf * 8 + lb * 2;
            __half* dst; float b0v, b1v; int cc;
            if (cn < 64) { dst = g_qh; cc = cn;      b0v = bq[cc]; b1v = bq[cc + 1]; }
            else         { dst = g_kh; cc = cn - 64; b0v = bk[cc]; b1v = bk[cc + 1]; }
            __half2 h0 = __floats2half2_rn(acc[mf][nf][0] + b0v, acc[mf][nf][1] + b1v);
            __half2 h1 = __floats2half2_rn(acc[mf][nf][2] + b0v, acc[mf][nf][3] + b1v);
            *(__half2*)(dst + (size_t)r0 * HD + cc)       = h0;
            *(__half2*)(dst + (size_t)(r0 + 8) * HD + cc) = h1;
        }
    }
}

// ---------------------------------------------------------------------------
// Kernel 2: scores = (q @ k^T) * 0.125 via fp16 mma, K=64 one-shot,
// with FUSED per-column partial softmax stats (max, sum-exp over 128 rows).
// CTA 128x128; 8 warps (2 in m x 4 in n), warp tile 64x32.
// ---------------------------------------------------------------------------
#define SCQ_BYTES (128 * 144)
#define SCRED_OFF (2 * SCQ_BYTES)            // 36864
#define SC_TOT    (SCRED_OFF + 8 * 32 * 8)   // + red[8][32] float2 = 38912

__global__ __launch_bounds__(256) void score_f16_kernel()
{
    extern __shared__ char smem[];
    const uint32_t smem_base = smem_u32(smem);
    const int tid  = threadIdx.x;
    const int wid  = tid >> 5;
    const int lane = tid & 31;
    const int la   = lane >> 2, lb = lane & 3;
    const int wm   = (wid & 1) * 64;
    const int wn   = (wid >> 1) * 32;
    const int b    = blockIdx.z;
    const int m0   = blockIdx.y * 128;
    const int n0   = blockIdx.x * 128;
    const __half* qg = g_qh + ((size_t)b * SEQ + m0) * HD;
    const __half* kg = g_kh + ((size_t)b * SEQ + n0) * HD;

    #pragma unroll
    for (int i = 0; i < 4; i++) {
        const int idx = tid + i * 256;
        const int row = idx >> 3, ch = idx & 7;
        cp_async16(smem_base + row * 144 + ch * 16, qg + (size_t)row * HD + ch * 8);
        cp_async16(smem_base + SCQ_BYTES + row * 144 + ch * 16, kg + (size_t)row * HD + ch * 8);
    }
    asm volatile("cp.async.commit_group;" ::: "memory");
    asm volatile("cp.async.wait_group 0;" ::: "memory");
    __syncthreads();

    const uint32_t* sQ = (const uint32_t*)smem;
    const uint32_t* sK = (const uint32_t*)(smem + SCQ_BYTES);

    float acc[4][4][4];
    #pragma unroll
    for (int i = 0; i < 4; i++)
        #pragma unroll
        for (int j = 0; j < 4; j++)
            #pragma unroll
            for (int q = 0; q < 4; q++) acc[i][j][q] = 0.0f;

    #pragma unroll
    for (int kf = 0; kf < 4; kf++) {
        uint32_t afr[4][4];
        #pragma unroll
        for (int mf = 0; mf < 4; mf++) {
            const int r = wm + mf * 16 + la;
            const int base = r * 36 + kf * 8 + lb;
            afr[mf][0] = sQ[base];
            afr[mf][1] = sQ[base + 8 * 36];
            afr[mf][2] = sQ[base + 4];
            afr[mf][3] = sQ[base + 8 * 36 + 4];
        }
        uint32_t bfr[4][2];
        #pragma unroll
        for (int nf = 0; nf < 4; nf++) {
            const int n = wn + nf * 8 + la;
            const int base = n * 36 + kf * 8 + lb;
            bfr[nf][0] = sK[base];
            bfr[nf][1] = sK[base + 4];
        }
        #pragma unroll
        for (int mf = 0; mf < 4; mf++)
            #pragma unroll
            for (int nf = 0; nf < 4; nf++)
                mma_f16(acc[mf][nf], afr[mf], bfr[nf]);
    }

    // scale + write fp32 scores
    float* S = g_s + (size_t)b * SEQ * SEQ;
    #pragma unroll
    for (int mf = 0; mf < 4; mf++) {
        const int r0 = m0 + wm + mf * 16 + la;
        #pragma unroll
        for (int nf = 0; nf < 4; nf++) {
            #pragma unroll
            for (int q = 0; q < 4; q++) acc[mf][nf][q] *= 0.125f;
            const int cn = n0 + wn + nf * 8 + lb * 2;
            *(float2*)(S + (size_t)r0 * SEQ + cn) =
                make_float2(acc[mf][nf][0], acc[mf][nf][1]);
            *(float2*)(S + (size_t)(r0 + 8) * SEQ + cn) =
                make_float2(acc[mf][nf][2], acc[mf][nf][3]);
        }
    }

    // fused partial column stats: per column over this tile's 128 rows
    __syncthreads();   // smem tiles no longer needed; red area is past them anyway
    float2* red = (float2*)(smem + SCRED_OFF);
    #pragma unroll
    for (int nf = 0; nf < 4; nf++) {
        #pragma unroll
        for (int e = 0; e < 2; e++) {
            float m = -3.0e38f;
            #pragma unroll
            for (int mf = 0; mf < 4; mf++) {
                m = fmaxf(m, acc[mf][nf][e]);
                m = fmaxf(m, acc[mf][nf][e + 2]);
            }
            #pragma unroll
            for (int off = 4; off <= 16; off <<= 1)
                m = fmaxf(m, __shfl_xor_sync(0xffffffffu, m, off));
            float z = 0.0f;
            #pragma unroll
            for (int mf = 0; mf < 4; mf++)
                z += __expf(acc[mf][nf][e] - m) + __expf(acc[mf][nf][e + 2] - m);
            #pragma unroll
            for (int off = 4; off <= 16; off <<= 1)
                z += __shfl_xor_sync(0xffffffffu, z, off);
            if (la == 0)
                red[wid * 32 + nf * 8 + lb * 2 + e] = make_float2(m, z);
        }
    }
    __syncthreads();
    if (tid < 128) {
        const int w0 = (tid >> 5) * 2;
        const int idx = tid & 31;
        float2 p0 = red[w0 * 32 + idx];
        float2 p1 = red[(w0 + 1) * 32 + idx];
        float m = fmaxf(p0.x, p1.x);
        float z = p0.y * __expf(p0.x - m) + p1.y * __expf(p1.x - m);
        const int gi = blockIdx.y * (BATCH * SEQ) + b * SEQ + n0 + tid;
        g_pm[gi] = m;
        g_pz[gi] = z;
    }
}

// ---------------------------------------------------------------------------
// Kernel 3: merge partials
// ---------------------------------------------------------------------------
__global__ __launch_bounds__(256) void colstat_merge_kernel()
{
    const int idx = blockIdx.x * 256 + threadIdx.x;
    float m = -3.0e38f;
    #pragma unroll
    for (int qc = 0; qc < NQC; qc++) m = fmaxf(m, g_pm[qc * (BATCH * SEQ) + idx]);
    float z = 0.0f;
    #pragma unroll
    for (int qc = 0; qc < NQC; qc++)
        z += g_pz[qc * (BATCH * SEQ) + idx] * __expf(g_pm[qc * (BATCH * SEQ) + idx] - m);
    g_m[idx]  = m;
    g_rz[idx] = 1.0f / z;
}

// ---------------------------------------------------------------------------
// Kernel 4: normalize: g_wh = fp16(exp(s - m_col) * rz_col)
// ---------------------------------------------------------------------------
__global__ __launch_bounds__(256) void norm_kernel()
{
    const int idx = (blockIdx.x * 256 + threadIdx.x) * 4;
    const int b = idx >> 22;
    const int k = idx & (SEQ - 1);
    const int base = b * SEQ + k;
    float4 v = *(const float4*)(g_s + idx);
    float w0 = __expf(v.x - g_m[base + 0]) * g_rz[base + 0];
    float w1 = __expf(v.y - g_m[base + 1]) * g_rz[base + 1];
    float w2 = __expf(v.z - g_m[base + 2]) * g_rz[base + 2];
    float w3 = __expf(v.w - g_m[base + 3]) * g_rz[base + 3];
    __half2 h0 = __floats2half2_rn(w0, w1);
    __half2 h1 = __floats2half2_rn(w2, w3);
    *(uint2*)(g_wh + idx) = make_uint2(*(uint32_t*)&h0, *(uint32_t*)&h1);
}

// ---------------------------------------------------------------------------
// Kernel 5: out[b] = W[b] @ h[b] via fp16 mma. CTA 128x256, K-chunk 64.
// ---------------------------------------------------------------------------
#define OA_BYTES (128 * 144)
#define OB_BYTES (256 * 144)
#define OSM_A(p) ((p) * (OA_BYTES + OB_BYTES))
#define OSM_B(p) (OSM_A(p) + OA_BYTES)
#define OSM_TOT  (2 * (OA_BYTES + OB_BYTES))

__global__ __launch_bounds__(256) void out_gemm_f16_kernel(float* __restrict__ out)
{
    extern __shared__ char smem[];
    const uint32_t smem_base = smem_u32(smem);
    const int tid  = threadIdx.x;
    const int wid  = tid >> 5;
    const int lane = tid & 31;
    const int la   = lane >> 2;
    const int lb   = lane & 3;
    const int wm   = (wid & 1) * 64;
    const int wn   = (wid >> 1) * 64;

    const int b  = blockIdx.z;
    const int m0 = blockIdx.y * 128;
    const int n0 = blockIdx.x * 256;
    const __half* A  = g_wh  + (size_t)b * SEQ * SEQ + (size_t)m0 * SEQ;
    const __half* Bt = g_hht + (size_t)b * EMB * SEQ + (size_t)n0 * SEQ;

    float acc[4][8][4];
    #pragma unroll
    for (int i = 0; i < 4; i++)
        #pragma unroll
        for (int j = 0; j < 8; j++)
            #pragma unroll
            for (int q = 0; q < 4; q++) acc[i][j][q] = 0.0f;

    #pragma unroll
    for (int i = 0; i < 4; i++) {
        const int idx = tid + i * 256;
        const int row = idx >> 3, ch = idx & 7;
        cp_async16(smem_base + OSM_A(0) + row * 144 + ch * 16,
                   A + (size_t)row * SEQ + ch * 8);
    }
    #pragma unroll
    for (int i = 0; i < 8; i++) {
        const int idx = tid + i * 256;
        const int row = idx >> 3, ch = idx & 7;
        cp_async16(smem_base + OSM_B(0) + row * 144 + ch * 16,
                   Bt + (size_t)row * SEQ + ch * 8);
    }
    asm volatile("cp.async.commit_group;" ::: "memory");

    for (int c = 0; c < SEQ / 64; ++c) {
        const int p = c & 1;
        if (c < SEQ / 64 - 1) {
            const int k0 = (c + 1) * 64;
            #pragma unroll
            for (int i = 0; i < 4; i++) {
                const int idx = tid + i * 256;
                const int row = idx >> 3, ch = idx & 7;
                cp_async16(smem_base + OSM_A(p ^ 1) + row * 144 + ch * 16,
                           A + (size_t)row * SEQ + k0 + ch * 8);
            }
            #pragma unroll
            for (int i = 0; i < 8; i++) {
                const int idx = tid + i * 256;
                const int row = idx >> 3, ch = idx & 7;
                cp_async16(smem_base + OSM_B(p ^ 1) + row * 144 + ch * 16,
                           Bt + (size_t)row * SEQ + k0 + ch * 8);
            }
            asm volatile("cp.async.commit_group;" ::: "memory");
            asm volatile("cp.async.wait_group 1;" ::: "memory");
        } else {
            asm volatile("cp.async.wait_group 0;" ::: "memory");
        }
        __syncthreads();

        const uint32_t* sA = (const uint32_t*)(smem + OSM_A(p));
        const uint32_t* sB = (const uint32_t*)(smem + OSM_B(p));

        #pragma unroll
        for (int kf = 0; kf < 4; kf++) {
            uint32_t afr[4][4];
            #pragma unroll
            for (int mf = 0; mf < 4; mf++) {
                const int r = wm + mf * 16 + la;
                const int base = r * 36 + kf * 8 + lb;
                afr[mf][0] = sA[base];
                afr[mf][1] = sA[base + 8 * 36];
                afr[mf][2] = sA[base + 4];
                afr[mf][3] = sA[base + 8 * 36 + 4];
            }
            uint32_t bfr[8][2];
            #pragma unroll
            for (int nf = 0; nf < 8; nf++) {
                const int n = wn + nf * 8 + la;
                const int base = n * 36 + kf * 8 + lb;
                bfr[nf][0] = sB[base];
                bfr[nf][1] = sB[base + 4];
            }
            #pragma unroll
            for (int mf = 0; mf < 4; mf++)
                #pragma unroll
                for (int nf = 0; nf < 8; nf++)
                    mma_f16(acc[mf][nf], afr[mf], bfr[nf]);
        }
        __syncthreads();
    }

    float* C = out + (size_t)b * SEQ * EMB;
    #pragma unroll
    for (int mf = 0; mf < 4; mf++) {
        const int r = m0 + wm + mf * 16 + la;
        #pragma unroll
        for (int nf = 0; nf < 8; nf++) {
            const int col = n0 + wn + nf * 8 + lb * 2;
            *(float2*)(C + (size_t)r * EMB + col)       = make_float2(acc[mf][nf][0], acc[mf][nf][1]);
            *(float2*)(C + (size_t)(r + 8) * EMB + col) = make_float2(acc[mf][nf][2], acc[mf][nf][3]);
        }
    }
}

// ---------------------------------------------------------------------------
extern "C" void kernel_launch(void* const* d_in, const int* in_sizes, int n_in,
                              void* d_out, int out_size)
{
    const float* h  = (const float*)d_in[0];
    const float* Wq = (const float*)d_in[1];
    const float* bq = (const float*)d_in[2];
    const float* Wk = (const float*)d_in[3];
    const float* bk = (const float*)d_in[4];
    float* out = (float*)d_out;

    static int smem_set = 0;
    if (!smem_set) {
        cudaFuncSetAttribute(out_gemm_f16_kernel,
                             cudaFuncAttributeMaxDynamicSharedMemorySize, OSM_TOT);
        cudaFuncSetAttribute(proj_f16_kernel,
                             cudaFuncAttributeMaxDynamicSharedMemorySize, PJ_TOT);
        cudaFuncSetAttribute(score_f16_kernel,
                             cudaFuncAttributeMaxDynamicSharedMemorySize, SC_TOT);
        smem_set = 1;
    }

    conv_h_kernel<<<dim3(SEQ / 32, EMB / 32, BATCH), dim3(32, 8)>>>(h);
    conv_w_kernel<<<128, 256>>>(Wq, Wk);
    proj_f16_kernel<<<(BATCH * SEQ) / 64, 256, PJ_TOT>>>(bq, bk);
    score_f16_kernel<<<dim3(SEQ / 128, SEQ / 128, BATCH), 256, SC_TOT>>>();
    colstat_merge_kernel<<<(BATCH * SEQ) / 256, 256>>>();
    norm_kernel<<<(BATCH * SEQ * SEQ) / (4 * 256), 256>>>();
    out_gemm_f16_kernel<<<dim3(EMB / 256, SEQ / 128, BATCH), 256, OSM_TOT>>>(out);
}